// round 6
// baseline (speedup 1.0000x reference)
#include <cuda_runtime.h>
#include <cuda_bf16.h>
#include <math.h>
#include <stdint.h>

#define N_TEST  8192
#define M_TRAIN 16384
#define D_DIM   512
#define BM      128
#define BN      128
#define BK      32
#define THREADS 256
#define CHUNK   256
#define NCHUNK  (M_TRAIN / CHUNK)            // 64
#define NROWT   (N_TEST / BM)                // 64
#define NUNITS  (NROWT * NCHUNK)             // 4096
#define TILES_U (CHUNK / BN)                 // 2
#define KSTEPS  (D_DIM / BK)                 // 16
#define USTAGES (TILES_U * KSTEPS)           // 32

#define AST 520                              // A smem row stride (u16)
#define BST 40                               // B smem row stride (u16)

#define SMEM_A        0
#define SMEM_A_BYTES  (BM * AST * 2)         // 133120
#define SMEM_B        SMEM_A_BYTES
#define B_STAGE_BYTES (BN * BST * 2)         // 10240
#define SMEM_YS       (SMEM_B + 4 * B_STAGE_BYTES)   // 174080
#define SMEM_RED      (SMEM_YS + 512)
#define SMEM_TOTAL    (SMEM_RED + 2048)

// ---------------- device scratch ----------------
__device__ __nv_bfloat16 g_Xb[N_TEST * D_DIM];
__device__ __nv_bfloat16 g_Yb[M_TRAIN * D_DIM];
__device__ float g_x2s[N_TEST];      // -0.5*log2(e)*||x||^2
__device__ float g_y2s[M_TRAIN];     // -0.5*log2(e)*||y||^2
__device__ float g_pm[NCHUNK * N_TEST];
__device__ float g_ps[NCHUNK * N_TEST];
__device__ unsigned g_unit_ctr;

// ---------------- helpers ----------------
__device__ __forceinline__ uint32_t smem_u32(const void* p) {
    uint32_t a;
    asm("{ .reg .u64 t; cvta.to.shared.u64 t, %1; cvt.u32.u64 %0, t; }" : "=r"(a) : "l"(p));
    return a;
}
__device__ __forceinline__ float ex2f(float x) {
    float y; asm("ex2.approx.ftz.f32 %0, %1;" : "=f"(y) : "f"(x)); return y;
}
__device__ __forceinline__ void cp16(uint32_t s, const void* g) {
    asm volatile("cp.async.cg.shared.global [%0], [%1], 16;" :: "r"(s), "l"(g));
}
#define CP_COMMIT() asm volatile("cp.async.commit_group;" ::: "memory")
#define CP_WAIT2()  asm volatile("cp.async.wait_group 2;" ::: "memory")

#define LDSM4(r, addr) \
    asm volatile("ldmatrix.sync.aligned.m8n8.x4.shared.b16 {%0,%1,%2,%3}, [%4];" \
        : "=r"((r)[0]), "=r"((r)[1]), "=r"((r)[2]), "=r"((r)[3]) : "r"(addr))
#define LDSM2(r, addr) \
    asm volatile("ldmatrix.sync.aligned.m8n8.x2.shared.b16 {%0,%1}, [%2];" \
        : "=r"((r)[0]), "=r"((r)[1]) : "r"(addr))

#define MMA16816(c, a, b) \
    asm volatile("mma.sync.aligned.m16n8k16.row.col.f32.bf16.bf16.f32 " \
        "{%0,%1,%2,%3},{%4,%5,%6,%7},{%8,%9},{%0,%1,%2,%3};" \
        : "+f"((c)[0]), "+f"((c)[1]), "+f"((c)[2]), "+f"((c)[3]) \
        : "r"((a)[0]), "r"((a)[1]), "r"((a)[2]), "r"((a)[3]), \
          "r"((b)[0]), "r"((b)[1]))

// ---------------------------------------------------------------------------
// Convert fp32 -> bf16 + scaled squared norms. One warp per row.
// Also resets the persistent kernel's unit counter.
// ---------------------------------------------------------------------------
__global__ void convert_kernel(const float* __restrict__ X,
                               const float* __restrict__ Y) {
    if (blockIdx.x == 0 && threadIdx.x == 0) g_unit_ctr = 0u;

    const float NHL2E = -0.5f * 1.4426950408889634f;
    int gw   = (blockIdx.x * blockDim.x + threadIdx.x) >> 5;
    int lane = threadIdx.x & 31;
    if (gw >= N_TEST + M_TRAIN) return;

    const float* src;
    __nv_bfloat16* dst;
    if (gw < N_TEST) { src = X + (size_t)gw * D_DIM; dst = g_Xb + (size_t)gw * D_DIM; }
    else { src = Y + (size_t)(gw - N_TEST) * D_DIM; dst = g_Yb + (size_t)(gw - N_TEST) * D_DIM; }

    const float4* p = (const float4*)(src + lane * 16);
    __nv_bfloat16 tmp[16];
    float s = 0.f;
#pragma unroll
    for (int j = 0; j < 4; ++j) {
        float4 v = p[j];
        s += v.x * v.x + v.y * v.y + v.z * v.z + v.w * v.w;
        tmp[4 * j + 0] = __float2bfloat16(v.x);
        tmp[4 * j + 1] = __float2bfloat16(v.y);
        tmp[4 * j + 2] = __float2bfloat16(v.z);
        tmp[4 * j + 3] = __float2bfloat16(v.w);
    }
    uint4* dv = (uint4*)(dst + lane * 16);
    dv[0] = ((uint4*)tmp)[0];
    dv[1] = ((uint4*)tmp)[1];
#pragma unroll
    for (int o = 16; o; o >>= 1) s += __shfl_xor_sync(0xffffffffu, s, o);
    if (lane == 0) {
        if (gw < N_TEST) g_x2s[gw] = NHL2E * s;
        else             g_y2s[gw - N_TEST] = NHL2E * s;
    }
}

// ---------------------------------------------------------------------------
// B stage fill: local stage l covers train rows [tb0 + (l/16)*BN, +BN),
// k chunk (l%16)*32.
// ---------------------------------------------------------------------------
__device__ __forceinline__ void fill_stage(uint32_t sb, int tb0, int l, int tid) {
    int buf = l & 3;
    int t   = l >> 4;
    int ks  = l & 15;
    int row = tid >> 2;
    int ch  = tid & 3;
    const __nv_bfloat16* gp =
        g_Yb + ((size_t)(tb0 + t * BN + row)) * D_DIM + ks * BK + ch * 8;
    uint32_t sa = sb + SMEM_B + buf * B_STAGE_BYTES + (uint32_t)(row * BST + ch * 8) * 2;
    cp16(sa, gp);
    cp16(sa + 64 * BST * 2, gp + (size_t)64 * D_DIM);
}

// ---------------------------------------------------------------------------
// Persistent fused kernel, 1 CTA/SM, dynamic unit stealing.
// Unit u: chunk = u & 63 (256 train cols), rt = u >> 6 (128 test rows).
// ---------------------------------------------------------------------------
__global__ __launch_bounds__(THREADS, 1)
void kde_mma_kernel() {
    extern __shared__ __align__(16) unsigned char smem[];
    const uint32_t sb = smem_u32(smem);

    const int tid  = threadIdx.x;
    const int lane = tid & 31;
    const int warp = tid >> 5;
    const int wm   = warp & 3;
    const int wn   = warp >> 2;

    const uint32_t aRowBase = sb + SMEM_A +
        (uint32_t)((wm * 32 + (lane & 15)) * AST + (lane >> 4) * 8) * 2;
    const uint32_t bLaneOff =
        (uint32_t)((wn * 64 + (lane & 7)) * BST + ((lane >> 3) & 1) * 8) * 2;

    float* ysf  = (float*)(smem + SMEM_YS);
    float* redm = (float*)(smem + SMEM_RED);
    float* reds = (float*)(smem + SMEM_RED + 1024);
    __shared__ unsigned s_u;
    const float L2E = 1.4426950408889634f;

    int cur_rt = -1;
    float x2p[4];

    for (;;) {
        if (tid == 0) s_u = atomicAdd(&g_unit_ctr, 1u);
        __syncthreads();
        const unsigned u = s_u;
        if (u >= NUNITS) break;

        const int chnk = (int)(u & (NCHUNK - 1));
        const int rt   = (int)(u >> 6);
        const int row0 = rt * BM;
        const int tb0  = chnk * CHUNK;

        if (rt != cur_rt) {
            cur_rt = rt;
            const __nv_bfloat16* gp = g_Xb + (size_t)row0 * D_DIM;
#pragma unroll
            for (int q = 0; q < 32; ++q) {
                int f = tid + q * THREADS;
                int r = f >> 6, c = f & 63;
                cp16(sb + SMEM_A + (uint32_t)(r * AST + c * 8) * 2,
                     gp + (size_t)r * D_DIM + c * 8);
            }
#pragma unroll
            for (int rg = 0; rg < 4; ++rg)
                x2p[rg] = g_x2s[row0 + wm * 32 + (rg >> 1) * 16 + (rg & 1) * 8 + (lane >> 2)];
        }
        CP_COMMIT();   // A (possibly empty) — keeps group accounting fixed

        fill_stage(sb, tb0, 0, tid); CP_COMMIT();
        fill_stage(sb, tb0, 1, tid); CP_COMMIT();
        fill_stage(sb, tb0, 2, tid); CP_COMMIT();

        // running logsumexp in f-domain (x2p folded in at the end)
        float mrun[4], srun[4];
#pragma unroll
        for (int rg = 0; rg < 4; ++rg) { mrun[rg] = -INFINITY; srun[rg] = 0.f; }

#pragma unroll 1
        for (int t = 0; t < TILES_U; ++t) {
            if (tid < BN) ysf[tid] = g_y2s[tb0 + t * BN + tid];

            float acc[2][8][4];
#pragma unroll
            for (int mt = 0; mt < 2; ++mt)
#pragma unroll
                for (int nt = 0; nt < 8; ++nt)
#pragma unroll
                    for (int i = 0; i < 4; ++i) acc[mt][nt][i] = 0.f;

#pragma unroll 1
            for (int ks = 0; ks < KSTEPS; ++ks) {
                const int l   = t * KSTEPS + ks;
                const int buf = l & 3;

                CP_WAIT2();            // stage l (and A on l=0) landed
                __syncthreads();
                if (l + 3 < USTAGES) fill_stage(sb, tb0, l + 3, tid);
                CP_COMMIT();           // empty commits at the tail keep invariant

                const uint32_t bBase = sb + SMEM_B + buf * B_STAGE_BYTES + bLaneOff;
                const uint32_t aCol  = (uint32_t)(ks * BK) * 2;
#pragma unroll
                for (int kk = 0; kk < 2; ++kk) {
                    uint32_t a[2][4];
                    uint32_t aaddr = aRowBase + aCol + kk * 32;
                    LDSM4(a[0], aaddr);
                    LDSM4(a[1], aaddr + 16 * AST * 2);
                    uint32_t b[8][2];
#pragma unroll
                    for (int nt = 0; nt < 8; ++nt)
                        LDSM2(b[nt], bBase + kk * 32 + nt * 8 * BST * 2);
#pragma unroll
                    for (int mt = 0; mt < 2; ++mt)
#pragma unroll
                        for (int nt = 0; nt < 8; ++nt)
                            MMA16816(acc[mt][nt], a[mt], b[nt]);
                }
            }

            // ---- epilogue: online logsumexp (f-domain, no x2p, no clamp) ----
            float2 yv[8];
#pragma unroll
            for (int nt = 0; nt < 8; ++nt)
                yv[nt] = *(const float2*)&ysf[wn * 64 + nt * 8 + (lane & 3) * 2];

#pragma unroll
            for (int rg = 0; rg < 4; ++rg) {
                const int mt = rg >> 1, hf = rg & 1;
                float e[16];
                float vmax = mrun[rg];
#pragma unroll
                for (int nt = 0; nt < 8; ++nt) {
                    float e0 = fmaf(acc[mt][nt][hf * 2 + 0], L2E, yv[nt].x);
                    float e1 = fmaf(acc[mt][nt][hf * 2 + 1], L2E, yv[nt].y);
                    e[nt * 2 + 0] = e0;
                    e[nt * 2 + 1] = e1;
                    vmax = fmaxf(vmax, fmaxf(e0, e1));
                }
                if (vmax > mrun[rg]) { srun[rg] *= ex2f(mrun[rg] - vmax); mrun[rg] = vmax; }
                float s0 = 0.f, s1 = 0.f;
#pragma unroll
                for (int j = 0; j < 16; j += 2) {
                    s0 += ex2f(e[j]     - mrun[rg]);
                    s1 += ex2f(e[j + 1] - mrun[rg]);
                }
                srun[rg] += s0 + s1;
            }
            __syncthreads();   // epilogue done before ys/buf reuse
        }

        // ---- per-unit reduction: quad shfl, then the 2 n-warps via smem ----
#pragma unroll
        for (int rg = 0; rg < 4; ++rg) {
            float m = mrun[rg] + x2p[rg];   // back to full exponent (log2 domain)
            float s = srun[rg];
#pragma unroll
            for (int off = 1; off <= 2; off <<= 1) {
                float mo = __shfl_xor_sync(0xffffffffu, m, off);
                float so = __shfl_xor_sync(0xffffffffu, s, off);
                float mx = fmaxf(m, mo);
                s = s * ex2f(m - mx) + so * ex2f(mo - mx);
                m = mx;
            }
            if ((lane & 3) == 0) {
                int r = wm * 32 + (rg >> 1) * 16 + (rg & 1) * 8 + (lane >> 2);
                redm[r * 2 + wn] = m;
                reds[r * 2 + wn] = s;
            }
        }
        __syncthreads();
        if (tid < BM) {
            float m0 = redm[tid * 2], m1 = redm[tid * 2 + 1];
            float s0 = reds[tid * 2], s1 = reds[tid * 2 + 1];
            float mx = fmaxf(m0, m1);
            float st = s0 * ex2f(m0 - mx) + s1 * ex2f(m1 - mx);
            g_pm[chnk * N_TEST + row0 + tid] = mx;
            g_ps[chnk * N_TEST + row0 + tid] = st;
        }
        __syncthreads();   // red + s_u free before next unit
    }
}

// ---------------------------------------------------------------------------
// Combine the NCHUNK partials per row: one warp per row, 2 chunks per lane.
// ---------------------------------------------------------------------------
__global__ void combine_kernel(float* __restrict__ out, float z) {
    int row  = (blockIdx.x * blockDim.x + threadIdx.x) >> 5;
    int lane = threadIdx.x & 31;
    if (row >= N_TEST) return;

    float m0 = g_pm[lane * N_TEST + row];
    float m1 = g_pm[(lane + 32) * N_TEST + row];
    float s0 = g_ps[lane * N_TEST + row];
    float s1 = g_ps[(lane + 32) * N_TEST + row];

    float m = fmaxf(m0, m1);
#pragma unroll
    for (int o = 16; o; o >>= 1) m = fmaxf(m, __shfl_xor_sync(0xffffffffu, m, o));
    float s = s0 * ex2f(m0 - m) + s1 * ex2f(m1 - m);
#pragma unroll
    for (int o = 16; o; o >>= 1) s += __shfl_xor_sync(0xffffffffu, s, o);

    if (lane == 0) out[row] = m * 0.6931471805599453f + logf(s) - z;
}

// ---------------------------------------------------------------------------
extern "C" void kernel_launch(void* const* d_in, const int* in_sizes, int n_in,
                              void* d_out, int out_size) {
    const float* X = (const float*)d_in[0];
    const float* Y = (const float*)d_in[1];
    float* out = (float*)d_out;

    float z = 0.5f * (float)D_DIM * logf(2.0f * 3.14159265358979323846f)
            + logf((float)M_TRAIN);

    static int nsm = 0;
    if (!nsm) {
        cudaDeviceGetAttribute(&nsm, cudaDevAttrMultiProcessorCount, 0);
        if (nsm <= 0) nsm = 148;
        cudaFuncSetAttribute(kde_mma_kernel,
                             cudaFuncAttributeMaxDynamicSharedMemorySize, SMEM_TOTAL);
    }

    int warps = N_TEST + M_TRAIN;
    convert_kernel<<<(warps * 32 + 255) / 256, 256>>>(X, Y);
    kde_mma_kernel<<<nsm, THREADS, SMEM_TOTAL>>>();
    combine_kernel<<<(N_TEST * 32 + 255) / 256, 256>>>(out, z);
}

// round 7
// speedup vs baseline: 1.1241x; 1.1241x over previous
#include <cuda_runtime.h>
#include <cuda_fp16.h>
#include <math.h>
#include <stdint.h>

#define N_TEST  8192
#define M_TRAIN 16384
#define D_DIM   512
#define BM      128
#define BN      128
#define BK      32
#define THREADS 256
#define CHUNK   1024
#define NCHUNK  (M_TRAIN / CHUNK)            // 16
#define NROWT   (N_TEST / BM)                // 64
#define NUNITS  (NROWT * NCHUNK)             // 1024
#define TILES_U (CHUNK / BN)                 // 8
#define KSTEPS  (D_DIM / BK)                 // 16
#define USTAGES (TILES_U * KSTEPS)           // 128

#define AST 520                              // A smem row stride (u16)
#define BST 40                               // B smem row stride (u16)

#define SMEM_A        0
#define SMEM_A_BYTES  (BM * AST * 2)         // 133120
#define SMEM_B        SMEM_A_BYTES
#define B_STAGE_BYTES (BN * BST * 2)         // 10240
#define SMEM_YS       (SMEM_B + 4 * B_STAGE_BYTES)   // 174080
#define SMEM_RED      (SMEM_YS + 512)
#define SMEM_TOTAL    (SMEM_RED + 2048)

// ---------------- device scratch ----------------
__device__ __half g_Xh[N_TEST * D_DIM];
__device__ __half g_Yh[M_TRAIN * D_DIM];
__device__ float g_x2s[N_TEST];      // -0.5*log2(e)*||x||^2
__device__ float g_y2s[M_TRAIN];     // -0.5*log2(e)*||y||^2
__device__ float g_pm[NCHUNK * N_TEST];
__device__ float g_ps[NCHUNK * N_TEST];

// ---------------- helpers ----------------
__device__ __forceinline__ uint32_t smem_u32(const void* p) {
    uint32_t a;
    asm("{ .reg .u64 t; cvta.to.shared.u64 t, %1; cvt.u32.u64 %0, t; }" : "=r"(a) : "l"(p));
    return a;
}
__device__ __forceinline__ float ex2f(float x) {
    float y; asm("ex2.approx.ftz.f32 %0, %1;" : "=f"(y) : "f"(x)); return y;
}
__device__ __forceinline__ void cp16(uint32_t s, const void* g) {
    asm volatile("cp.async.cg.shared.global [%0], [%1], 16;" :: "r"(s), "l"(g));
}
#define CP_COMMIT() asm volatile("cp.async.commit_group;" ::: "memory")
#define CP_WAIT2()  asm volatile("cp.async.wait_group 2;" ::: "memory")

#define LDSM4(r, addr) \
    asm volatile("ldmatrix.sync.aligned.m8n8.x4.shared.b16 {%0,%1,%2,%3}, [%4];" \
        : "=r"((r)[0]), "=r"((r)[1]), "=r"((r)[2]), "=r"((r)[3]) : "r"(addr))
#define LDSM2(r, addr) \
    asm volatile("ldmatrix.sync.aligned.m8n8.x2.shared.b16 {%0,%1}, [%2];" \
        : "=r"((r)[0]), "=r"((r)[1]) : "r"(addr))

// fp16 inputs, fp16 accumulate (2 regs C/D)
#define MMA16816H(c, a, b) \
    asm volatile("mma.sync.aligned.m16n8k16.row.col.f16.f16.f16.f16 " \
        "{%0,%1},{%2,%3,%4,%5},{%6,%7},{%0,%1};" \
        : "+r"((c)[0]), "+r"((c)[1]) \
        : "r"((a)[0]), "r"((a)[1]), "r"((a)[2]), "r"((a)[3]), \
          "r"((b)[0]), "r"((b)[1]))

// ---------------------------------------------------------------------------
// Convert fp32 -> fp16 + scaled squared norms. One warp per row.
// ---------------------------------------------------------------------------
__global__ void convert_kernel(const float* __restrict__ X,
                               const float* __restrict__ Y) {
    const float NHL2E = -0.5f * 1.4426950408889634f;
    int gw   = (blockIdx.x * blockDim.x + threadIdx.x) >> 5;
    int lane = threadIdx.x & 31;
    if (gw >= N_TEST + M_TRAIN) return;

    const float* src;
    __half* dst;
    if (gw < N_TEST) { src = X + (size_t)gw * D_DIM; dst = g_Xh + (size_t)gw * D_DIM; }
    else { src = Y + (size_t)(gw - N_TEST) * D_DIM; dst = g_Yh + (size_t)(gw - N_TEST) * D_DIM; }

    const float4* p = (const float4*)(src + lane * 16);
    __half tmp[16];
    float s = 0.f;
#pragma unroll
    for (int j = 0; j < 4; ++j) {
        float4 v = p[j];
        s += v.x * v.x + v.y * v.y + v.z * v.z + v.w * v.w;
        tmp[4 * j + 0] = __float2half_rn(v.x);
        tmp[4 * j + 1] = __float2half_rn(v.y);
        tmp[4 * j + 2] = __float2half_rn(v.z);
        tmp[4 * j + 3] = __float2half_rn(v.w);
    }
    uint4* dv = (uint4*)(dst + lane * 16);
    dv[0] = ((uint4*)tmp)[0];
    dv[1] = ((uint4*)tmp)[1];
#pragma unroll
    for (int o = 16; o; o >>= 1) s += __shfl_xor_sync(0xffffffffu, s, o);
    if (lane == 0) {
        if (gw < N_TEST) g_x2s[gw] = NHL2E * s;
        else             g_y2s[gw - N_TEST] = NHL2E * s;
    }
}

// ---------------------------------------------------------------------------
// B stage fill: local stage l covers train rows [tb0 + (l/16)*BN, +BN),
// k chunk (l%16)*32.
// ---------------------------------------------------------------------------
__device__ __forceinline__ void fill_stage(uint32_t sb, int tb0, int l, int tid) {
    int buf = l & 3;
    int t   = l >> 4;
    int ks  = l & 15;
    int row = tid >> 2;
    int ch  = tid & 3;
    const __half* gp =
        g_Yh + ((size_t)(tb0 + t * BN + row)) * D_DIM + ks * BK + ch * 8;
    uint32_t sa = sb + SMEM_B + buf * B_STAGE_BYTES + (uint32_t)(row * BST + ch * 8) * 2;
    cp16(sa, gp);
    cp16(sa + 64 * BST * 2, gp + (size_t)64 * D_DIM);
}

// ---------------------------------------------------------------------------
// Persistent fused kernel: static contiguous unit slices (R4 schedule),
// fp16 MMA with fp16 accumulators.
// ---------------------------------------------------------------------------
__global__ __launch_bounds__(THREADS, 1)
void kde_mma_kernel() {
    extern __shared__ __align__(16) unsigned char smem[];
    const uint32_t sb = smem_u32(smem);

    const int tid  = threadIdx.x;
    const int lane = tid & 31;
    const int warp = tid >> 5;
    const int wm   = warp & 3;
    const int wn   = warp >> 2;

    const int g  = gridDim.x;
    const int u0 = (int)(((long long)blockIdx.x * NUNITS) / g);
    const int u1 = (int)(((long long)(blockIdx.x + 1) * NUNITS) / g);

    const uint32_t aRowBase = sb + SMEM_A +
        (uint32_t)((wm * 32 + (lane & 15)) * AST + (lane >> 4) * 8) * 2;
    const uint32_t bLaneOff =
        (uint32_t)((wn * 64 + (lane & 7)) * BST + ((lane >> 3) & 1) * 8) * 2;

    float* ysf  = (float*)(smem + SMEM_YS);
    float* redm = (float*)(smem + SMEM_RED);
    float* reds = (float*)(smem + SMEM_RED + 1024);
    const float L2E = 1.4426950408889634f;

    int cur_rt = -1;
    float x2p[4];

    for (int u = u0; u < u1; ++u) {
        const int rt   = u >> 4;
        const int chnk = u & 15;
        const int row0 = rt * BM;
        const int tb0  = chnk * CHUNK;

        if (rt != cur_rt) {
            cur_rt = rt;
            const __half* gp = g_Xh + (size_t)row0 * D_DIM;
#pragma unroll
            for (int q = 0; q < 32; ++q) {
                int f = tid + q * THREADS;
                int r = f >> 6, c = f & 63;
                cp16(sb + SMEM_A + (uint32_t)(r * AST + c * 8) * 2,
                     gp + (size_t)r * D_DIM + c * 8);
            }
            CP_COMMIT();
#pragma unroll
            for (int rg = 0; rg < 4; ++rg)
                x2p[rg] = g_x2s[row0 + wm * 32 + (rg >> 1) * 16 + (rg & 1) * 8 + (lane >> 2)];
        }

        fill_stage(sb, tb0, 0, tid); CP_COMMIT();
        fill_stage(sb, tb0, 1, tid); CP_COMMIT();
        fill_stage(sb, tb0, 2, tid); CP_COMMIT();

        // running logsumexp in f-domain (x2p folded in at the end)
        float mrun[4], srun[4];
#pragma unroll
        for (int rg = 0; rg < 4; ++rg) { mrun[rg] = -INFINITY; srun[rg] = 0.f; }

#pragma unroll 1
        for (int t = 0; t < TILES_U; ++t) {
            if (tid < BN) ysf[tid] = g_y2s[tb0 + t * BN + tid];

            uint32_t acc[2][8][2];
#pragma unroll
            for (int mt = 0; mt < 2; ++mt)
#pragma unroll
                for (int nt = 0; nt < 8; ++nt) { acc[mt][nt][0] = 0u; acc[mt][nt][1] = 0u; }

#pragma unroll 1
            for (int ks = 0; ks < KSTEPS; ++ks) {
                const int l   = t * KSTEPS + ks;
                const int buf = l & 3;

                CP_WAIT2();            // stage l (and A, on first step) landed
                __syncthreads();
                if (l + 3 < USTAGES) fill_stage(sb, tb0, l + 3, tid);
                CP_COMMIT();           // empty commits at the tail keep invariant

                const uint32_t bBase = sb + SMEM_B + buf * B_STAGE_BYTES + bLaneOff;
                const uint32_t aCol  = (uint32_t)(ks * BK) * 2;
#pragma unroll
                for (int kk = 0; kk < 2; ++kk) {
                    uint32_t a[2][4];
                    uint32_t aaddr = aRowBase + aCol + kk * 32;
                    LDSM4(a[0], aaddr);
                    LDSM4(a[1], aaddr + 16 * AST * 2);
                    uint32_t b[8][2];
#pragma unroll
                    for (int nt = 0; nt < 8; ++nt)
                        LDSM2(b[nt], bBase + kk * 32 + nt * 8 * BST * 2);
#pragma unroll
                    for (int mt = 0; mt < 2; ++mt)
#pragma unroll
                        for (int nt = 0; nt < 8; ++nt)
                            MMA16816H(acc[mt][nt], a[mt], b[nt]);
                }
            }

            // ---- epilogue: unpack fp16 accums, online logsumexp (f-domain) ----
            float2 yv[8];
#pragma unroll
            for (int nt = 0; nt < 8; ++nt)
                yv[nt] = *(const float2*)&ysf[wn * 64 + nt * 8 + (lane & 3) * 2];

#pragma unroll
            for (int rg = 0; rg < 4; ++rg) {
                const int mt = rg >> 1, hf = rg & 1;
                float e[16];
                float vmax = mrun[rg];
#pragma unroll
                for (int nt = 0; nt < 8; ++nt) {
                    float2 d = __half22float2(*(const __half2*)&acc[mt][nt][hf]);
                    float e0 = fmaf(d.x, L2E, yv[nt].x);
                    float e1 = fmaf(d.y, L2E, yv[nt].y);
                    e[nt * 2 + 0] = e0;
                    e[nt * 2 + 1] = e1;
                    vmax = fmaxf(vmax, fmaxf(e0, e1));
                }
                if (vmax > mrun[rg]) { srun[rg] *= ex2f(mrun[rg] - vmax); mrun[rg] = vmax; }
                float s0 = 0.f, s1 = 0.f;
#pragma unroll
                for (int j = 0; j < 16; j += 2) {
                    s0 += ex2f(e[j]     - mrun[rg]);
                    s1 += ex2f(e[j + 1] - mrun[rg]);
                }
                srun[rg] += s0 + s1;
            }
            __syncthreads();   // epilogue done before ys/buf reuse
        }

        // ---- per-unit reduction: quad shfl, then the 2 n-warps via smem ----
#pragma unroll
        for (int rg = 0; rg < 4; ++rg) {
            float m = mrun[rg] + x2p[rg];   // fold row constant back in
            float s = srun[rg];
#pragma unroll
            for (int off = 1; off <= 2; off <<= 1) {
                float mo = __shfl_xor_sync(0xffffffffu, m, off);
                float so = __shfl_xor_sync(0xffffffffu, s, off);
                float mx = fmaxf(m, mo);
                s = s * ex2f(m - mx) + so * ex2f(mo - mx);
                m = mx;
            }
            if ((lane & 3) == 0) {
                int r = wm * 32 + (rg >> 1) * 16 + (rg & 1) * 8 + (lane >> 2);
                redm[r * 2 + wn] = m;
                reds[r * 2 + wn] = s;
            }
        }
        __syncthreads();
        if (tid < BM) {
            float m0 = redm[tid * 2], m1 = redm[tid * 2 + 1];
            float s0 = reds[tid * 2], s1 = reds[tid * 2 + 1];
            float mx = fmaxf(m0, m1);
            float st = s0 * ex2f(m0 - mx) + s1 * ex2f(m1 - mx);
            g_pm[chnk * N_TEST + row0 + tid] = mx;
            g_ps[chnk * N_TEST + row0 + tid] = st;
        }
        __syncthreads();   // red free before next unit's epilogue
    }
}

// ---------------------------------------------------------------------------
// Combine the NCHUNK train-chunk partials per row. m is in log2 domain.
// ---------------------------------------------------------------------------
__global__ void combine_kernel(float* __restrict__ out, float z) {
    int i = blockIdx.x * blockDim.x + threadIdx.x;
    if (i >= N_TEST) return;
    float mx = -INFINITY;
#pragma unroll
    for (int c = 0; c < NCHUNK; ++c) mx = fmaxf(mx, g_pm[c * N_TEST + i]);
    float st = 0.f;
#pragma unroll
    for (int c = 0; c < NCHUNK; ++c)
        st += g_ps[c * N_TEST + i] * ex2f(g_pm[c * N_TEST + i] - mx);
    out[i] = mx * 0.6931471805599453f + logf(st) - z;
}

// ---------------------------------------------------------------------------
extern "C" void kernel_launch(void* const* d_in, const int* in_sizes, int n_in,
                              void* d_out, int out_size) {
    const float* X = (const float*)d_in[0];
    const float* Y = (const float*)d_in[1];
    float* out = (float*)d_out;

    float z = 0.5f * (float)D_DIM * logf(2.0f * 3.14159265358979323846f)
            + logf((float)M_TRAIN);

    static int nsm = 0;
    if (!nsm) {
        cudaDeviceGetAttribute(&nsm, cudaDevAttrMultiProcessorCount, 0);
        if (nsm <= 0) nsm = 148;
        cudaFuncSetAttribute(kde_mma_kernel,
                             cudaFuncAttributeMaxDynamicSharedMemorySize, SMEM_TOTAL);
    }

    int warps = N_TEST + M_TRAIN;
    convert_kernel<<<(warps * 32 + 255) / 256, 256>>>(X, Y);
    kde_mma_kernel<<<nsm, THREADS, SMEM_TOTAL>>>();
    combine_kernel<<<(N_TEST + 255) / 256, 256>>>(out, z);
}